// round 7
// baseline (speedup 1.0000x reference)
#include <cuda_runtime.h>
#include <cuda_fp16.h>
#include <cstdint>

#define KK     9
#define IN_C   32
#define OUT_C  64
#define HWDIM  256
#define NTH    256

// dynamic smem byte layout (64B-pitch XOR-swizzled rows):
//  xs: 774 rows (3*258) x 64B = 49536   (x fp16, rows = spatial col, 16 half2 words/row)
//  ws: 2 stages x 12288 (3*64 rows x 64B)
//  ds: 3*260 floats = 3120
//  pk: 2 stages x 1536 (3*128 words)
#define OFF_WS 49536
#define WS_STAGE 12288
#define OFF_DS (OFF_WS + 2 * WS_STAGE)      // 74112
#define OFF_PK (OFF_DS + 3120)              // 77232
#define PK_STAGE 1536
#define SMEM_BYTES (OFF_PK + 2 * PK_STAGE)  // 80304
#define OB_PITCH 260                        // epilogue obuf [64][260] floats (overlay)

// weights pre-swizzled into fragment word order: g_wth2[((p*3+i)*64+o)*16 + pos]
__device__ uint32_t g_wth2[KK * 3 * OUT_C * 16];

__global__ void prep_weights(const float* __restrict__ w0,
                             const float* __restrict__ w1,
                             const float* __restrict__ w2) {
    int idx = blockIdx.x * blockDim.x + threadIdx.x;
    if (idx >= KK * 3 * OUT_C * 16) return;
    int p = idx / 3072;
    int r = idx % 3072;
    int i = r >> 10;
    int o = (r >> 4) & 63;
    int w = r & 15;
    // word w -> channel pair: kg=w>>3, t=(w>>1)&3, h=w&1 ; cp = 8kg+4h+t
    int kg = w >> 3, t = (w >> 1) & 3, hb = w & 1;
    int cp = 8 * kg + 4 * hb + t;
    const float* wsrc = (i == 0) ? w0 : (i == 1) ? w1 : w2;
    float v0 = wsrc[(o * IN_C + 2 * cp) * KK + p];
    float v1 = wsrc[(o * IN_C + 2 * cp + 1) * KK + p];
    __half2 hh = __halves2half2(__float2half(v0), __float2half(v1));
    int pos = w ^ (((o >> 1) & 1) << 3);
    g_wth2[((p * 3 + i) * 64 + o) * 16 + pos] = *(uint32_t*)&hh;
}

__device__ __forceinline__ void mma_f16(float* d, const uint32_t* a, const uint32_t* b) {
    asm volatile(
        "mma.sync.aligned.m16n8k16.row.col.f32.f16.f16.f32 "
        "{%0,%1,%2,%3}, {%4,%5,%6,%7}, {%8,%9}, {%0,%1,%2,%3};"
        : "+f"(d[0]), "+f"(d[1]), "+f"(d[2]), "+f"(d[3])
        : "r"(a[0]), "r"(a[1]), "r"(a[2]), "r"(a[3]), "r"(b[0]), "r"(b[1]));
}

__device__ __forceinline__ uint32_t hmul2u(uint32_t a, uint32_t m) {
    __half2 r = __hmul2(*(__half2*)&a, *(__half2*)&m);
    return *(uint32_t*)&r;
}

__global__ void __launch_bounds__(NTH, 2)
conv25d_sw(const float* __restrict__ x,
           const float* __restrict__ disp,
           const float* __restrict__ fxp,
           const float* __restrict__ blp,
           float* __restrict__ out) {
    extern __shared__ __align__(16) char smem[];
    float* ds = (float*)(smem + OFF_DS);

    const int tid  = threadIdx.x;
    const int lane = tid & 31;
    const int wrp  = tid >> 5;
    const int g    = lane >> 2;
    const int cl   = lane & 3;
    const int mw   = wrp & 3;           // M group: 64 px
    const int oh   = wrp >> 2;          // N half
    const int jbase = mw << 6;
    const int obase = oh << 5;

    const int n = blockIdx.x >> 8;      // 512 CTAs: full 256-px row each
    const int h = blockIdx.x & 255;

    const float* xb = x + (size_t)n * IN_C * (HWDIM * HWDIM);
    const float* db = disp + (size_t)n * (HWDIM * HWDIM);

    // ---- stage disp rows: ds[di][j], j = gx+1 in 0..257 ----
    for (int e = tid; e < 3 * 258; e += NTH) {
        int di = e / 258, j = e % 258;
        int gy = h + di - 1, gx = j - 1;
        float v = 0.0f;
        if (gy >= 0 && gy < HWDIM && gx >= 0 && gx < HWDIM) v = db[gy * HWDIM + gx];
        ds[di * 260 + j] = v;
    }

    // ---- stage x (fp16, swizzled 64B rows). row = di*258 + j ----
    for (int t = wrp; t < 6 * 65; t += 8) {
        int plane = t / 65;             // (di, cph)
        int jb4   = (t % 65) * 4;
        int di = plane >> 1, cph = plane & 1;
        int cp = cph * 8 + (lane >> 2);
        int j  = jb4 + (lane & 3);
        if (j < 258) {
            int gy = h + di - 1, gx = j - 1;
            float v0 = 0.0f, v1 = 0.0f;
            if (gy >= 0 && gy < HWDIM && gx >= 0 && gx < HWDIM) {
                v0 = xb[(2 * cp) * (HWDIM * HWDIM) + gy * HWDIM + gx];
                v1 = xb[(2 * cp + 1) * (HWDIM * HWDIM) + gy * HWDIM + gx];
            }
            __half2 hh = __halves2half2(__float2half(v0), __float2half(v1));
            int row = di * 258 + j;
            int w = ((cp >> 3) << 3) | ((cp & 3) << 1) | ((cp >> 2) & 1);
            int pos = w ^ (((row >> 1) & 1) << 3);
            *(uint32_t*)(smem + row * 64 + pos * 4) = *(uint32_t*)&hh;
        }
    }
    __syncthreads();

    // ---- per-pixel center quantities (thread = pixel, exact fp32) ----
    const float fxv = fxp[n];
    const float bf  = __fmul_rn(blp[n], fxv);
    const float dC  = ds[260 + 1 + tid];
    const bool validC = (dC != 0.0f);
    const float depthC = __fdiv_rn(bf, fminf(fmaxf(validC ? dC : 0.0f, 0.01f), 256.0f));
    const float grv    = __fdiv_rn(__fmul_rn(16.0f, depthC), fxv);
    const float halfv  = __fmul_rn(grv, 0.5f);

    float acc[4][4][4];
#pragma unroll
    for (int mt = 0; mt < 4; mt++)
#pragma unroll
        for (int n8 = 0; n8 < 4; n8++)
#pragma unroll
            for (int q = 0; q < 4; q++) acc[mt][n8][q] = 0.0f;

    int s = 0;
    for (int p = 0; p < KK; p++) {
        const int di = p / 3, dj = p % 3;

        // ---- producer: masks for this p (bit-exact fp32), pack pairs via shfl ----
        {
            float dp = ds[di * 260 + dj + tid];
            const bool valid = (dp != 0.0f) && validC;
            const float depth = __fdiv_rn(bf, fminf(fmaxf(valid ? dp : 0.0f, 0.01f), 256.0f));
            float m[3];
            m[0] = (fabsf(__fsub_rn(depth, __fadd_rn(depthC, grv))) <= halfv) ? 1.0f : 0.0f;
            const float ind = (fabsf(__fsub_rn(depth, depthC)) <= halfv) ? 1.0f : 0.0f;
            m[1] = valid ? ind : 1.0f;
            m[2] = (fabsf(__fsub_rn(depth, __fsub_rn(depthC, grv))) <= halfv) ? 1.0f : 0.0f;
            uint32_t* pkw = (uint32_t*)(smem + OFF_PK + s * PK_STAGE);
            const bool lo = ((tid >> 3) & 1) == 0;       // pairs (P, P+8)
            const int widx = ((tid >> 4) << 3) | (tid & 7);   // mt16*8 + g
#pragma unroll
            for (int i = 0; i < 3; i++) {
                float pm = __shfl_xor_sync(0xffffffffu, m[i], 8);
                if (lo) {
                    __half2 hh = __halves2half2(__float2half(m[i]), __float2half(pm));
                    pkw[i * 128 + widx] = *(uint32_t*)&hh;
                }
            }
        }
        // ---- producer: stage weights for this p into ws[s] (linear copy) ----
        {
            const uint32_t* src = g_wth2 + p * 3072;
            uint32_t* dst = (uint32_t*)(smem + OFF_WS + s * WS_STAGE);
#pragma unroll
            for (int k = 0; k < 12; k++) dst[tid + k * NTH] = src[tid + k * NTH];
        }
        __syncthreads();

        // ---- consumer ----
        const int rowb = di * 258 + dj + jbase;
        const uint32_t* pku = (const uint32_t*)(smem + OFF_PK + s * PK_STAGE);
        const char* wsb = smem + OFF_WS + s * WS_STAGE;

#pragma unroll
        for (int ks = 0; ks < 2; ks++) {
            // A fragments for all 4 m-tiles (LDS.64 pairs)
            uint32_t afr[4][4];
#pragma unroll
            for (int mt = 0; mt < 4; mt++) {
                int r0 = rowb + mt * 16 + g;
                int pos0 = (ks * 8 + cl * 2) ^ (((r0 >> 1) & 1) << 3);
                uint2 loa = *(const uint2*)(smem + r0 * 64 + pos0 * 4);
                int r1 = r0 + 8;
                int pos1 = (ks * 8 + cl * 2) ^ (((r1 >> 1) & 1) << 3);
                uint2 hia = *(const uint2*)(smem + r1 * 64 + pos1 * 4);
                afr[mt][0] = loa.x; afr[mt][2] = loa.y;   // row r0: k, k+8
                afr[mt][1] = hia.x; afr[mt][3] = hia.y;   // row r0+8
            }
#pragma unroll
            for (int i = 0; i < 3; i++) {
                uint32_t pw[4];
#pragma unroll
                for (int mt = 0; mt < 4; mt++)
                    pw[mt] = pku[i * 128 + (mw * 4 + mt) * 8 + g];
                if (!__any_sync(0xffffffffu, (pw[0] | pw[1] | pw[2] | pw[3]) != 0u))
                    continue;

                uint32_t bfr[4][2];
#pragma unroll
                for (int n8 = 0; n8 < 4; n8++) {
                    int o = obase + n8 * 8 + g;
                    int pos = (ks * 8 + cl * 2) ^ (((o >> 1) & 1) << 3);
                    uint2 bv = *(const uint2*)(wsb + (i * 64 + o) * 64 + pos * 4);
                    bfr[n8][0] = bv.x; bfr[n8][1] = bv.y;
                }
#pragma unroll
                for (int mt = 0; mt < 4; mt++) {
                    __half2 pp = *(__half2*)&pw[mt];
                    __half2 l2 = __half2half2(__low2half(pp));
                    __half2 h2 = __half2half2(__high2half(pp));
                    uint32_t ml = *(uint32_t*)&l2, mh = *(uint32_t*)&h2;
                    uint32_t am[4];
                    am[0] = hmul2u(afr[mt][0], ml);
                    am[1] = hmul2u(afr[mt][1], mh);
                    am[2] = hmul2u(afr[mt][2], ml);
                    am[3] = hmul2u(afr[mt][3], mh);
#pragma unroll
                    for (int n8 = 0; n8 < 4; n8++)
                        mma_f16(acc[mt][n8], am, bfr[n8]);
                }
            }
        }
        s ^= 1;
    }

    // ---- epilogue: acc -> smem transpose -> coalesced float4 stores ----
    __syncthreads();
    float* obuf = (float*)smem;   // [o][j], pitch 260
#pragma unroll
    for (int mt = 0; mt < 4; mt++) {
#pragma unroll
        for (int n8 = 0; n8 < 4; n8++) {
            int o = obase + n8 * 8 + cl * 2;
            int j = jbase + mt * 16 + g;
            obuf[o * OB_PITCH + j]           = acc[mt][n8][0];
            obuf[(o + 1) * OB_PITCH + j]     = acc[mt][n8][1];
            obuf[o * OB_PITCH + j + 8]       = acc[mt][n8][2];
            obuf[(o + 1) * OB_PITCH + j + 8] = acc[mt][n8][3];
        }
    }
    __syncthreads();
#pragma unroll
    for (int it = 0; it < 16; it++) {
        int e  = tid + it * NTH;   // (o, j4) : 64 x 64
        int o  = e >> 6;
        int j4 = e & 63;
        float4 v = *(const float4*)&obuf[o * OB_PITCH + j4 * 4];
        *(float4*)&out[((size_t)(n * OUT_C + o)) * (HWDIM * HWDIM)
                       + h * HWDIM + j4 * 4] = v;
    }
}

extern "C" void kernel_launch(void* const* d_in, const int* in_sizes, int n_in,
                              void* d_out, int out_size) {
    const float* x    = (const float*)d_in[0];
    const float* disp = (const float*)d_in[1];
    const float* fx   = (const float*)d_in[2];
    const float* bl   = (const float*)d_in[3];
    const float* w0   = (const float*)d_in[4];
    const float* w1   = (const float*)d_in[5];
    const float* w2   = (const float*)d_in[6];
    float* out = (float*)d_out;

    prep_weights<<<(KK * 3 * OUT_C * 16 + 255) / 256, 256>>>(w0, w1, w2);

    cudaFuncSetAttribute(conv25d_sw, cudaFuncAttributeMaxDynamicSharedMemorySize, SMEM_BYTES);
    conv25d_sw<<<512, NTH, SMEM_BYTES>>>(x, disp, fx, bl, out);
}

// round 8
// speedup vs baseline: 1.2783x; 1.2783x over previous
#include <cuda_runtime.h>
#include <cuda_fp16.h>
#include <cstdint>

#define KK     9
#define IN_C   32
#define OUT_C  64
#define HWDIM  256
#define NTH    256

// smem: xs 390 rows (3*130) x 64B = 24960 ; ds 3*132 floats = 1584 ; pk 9*192 words = 6912
#define OFF_DS 24960
#define OFF_PK (OFF_DS + 1584)      // 26544
#define SMEM_BYTES 33792            // >= max(26544+6912, obuf 64*132*4)
#define OB_PITCH 132

// B fragments pre-packed in lane word order:
// g_wfrag[((p*3+i)*64 + o)*16 + w], w = ks*8 + cl*2 + sub  <->  cp = ks*8 + cl + sub*4
__device__ uint32_t g_wfrag[KK * 3 * OUT_C * 16];

__global__ void prep_weights(const float* __restrict__ w0,
                             const float* __restrict__ w1,
                             const float* __restrict__ w2) {
    int idx = blockIdx.x * blockDim.x + threadIdx.x;
    if (idx >= KK * 3 * OUT_C * 16) return;
    int p = idx / 3072;
    int r = idx % 3072;
    int i = r >> 10;
    int o = (r >> 4) & 63;
    int w = r & 15;
    int ks = w >> 3, clw = (w >> 1) & 3, sub = w & 1;
    int cp = ks * 8 + clw + sub * 4;
    const float* wsrc = (i == 0) ? w0 : (i == 1) ? w1 : w2;
    float v0 = wsrc[(o * IN_C + 2 * cp) * KK + p];
    float v1 = wsrc[(o * IN_C + 2 * cp + 1) * KK + p];
    __half2 hh = __halves2half2(__float2half(v0), __float2half(v1));
    g_wfrag[idx] = *(uint32_t*)&hh;
}

__device__ __forceinline__ void mma_f16(float* d, const uint32_t* a, const uint32_t* b) {
    asm volatile(
        "mma.sync.aligned.m16n8k16.row.col.f32.f16.f16.f32 "
        "{%0,%1,%2,%3}, {%4,%5,%6,%7}, {%8,%9}, {%0,%1,%2,%3};"
        : "+f"(d[0]), "+f"(d[1]), "+f"(d[2]), "+f"(d[3])
        : "r"(a[0]), "r"(a[1]), "r"(a[2]), "r"(a[3]), "r"(b[0]), "r"(b[1]));
}

__device__ __forceinline__ uint32_t hmul2u(uint32_t a, uint32_t m) {
    __half2 r = __hmul2(*(__half2*)&a, *(__half2*)&m);
    return *(uint32_t*)&r;
}

__global__ void __launch_bounds__(NTH, 3)
conv25d_l1(const float* __restrict__ x,
           const float* __restrict__ disp,
           const float* __restrict__ fxp,
           const float* __restrict__ blp,
           float* __restrict__ out) {
    __shared__ __align__(16) char smem[SMEM_BYTES];
    float*    ds  = (float*)(smem + OFF_DS);
    uint32_t* pkw = (uint32_t*)(smem + OFF_PK);

    const int tid  = threadIdx.x;
    const int lane = tid & 31;
    const int wrp  = tid >> 5;
    const int g    = lane >> 2;
    const int cl   = lane & 3;
    const int jb   = (wrp & 3) << 5;    // pixel group base
    const int obase = (wrp >> 2) << 5;  // out-channel half

    const int b   = blockIdx.x;         // 1024 CTAs
    const int n   = b >> 9;
    const int rem = b & 511;
    const int h   = rem >> 1;
    const int wb  = (rem & 1) << 7;

    const float* xb = x + (size_t)n * IN_C * (HWDIM * HWDIM);
    const float* db = disp + (size_t)n * (HWDIM * HWDIM);

    // ---- stage disp rows: ds[di][j], j = gx - (wb-1), 130 cols ----
    for (int e = tid; e < 3 * 130; e += NTH) {
        int di = e / 130, j = e % 130;
        int gy = h + di - 1, gx = wb - 1 + j;
        float v = 0.0f;
        if (gy >= 0 && gy < HWDIM && gx >= 0 && gx < HWDIM) v = db[gy * HWDIM + gx];
        ds[di * 132 + j] = v;
    }

    // ---- stage x (fp16, 64B-pitch XOR-swizzled rows), row = di*130 + j ----
    // conflict-free STS: lanes = 4 cols x 8 channel-pairs
    for (int t = wrp; t < 6 * 33; t += 8) {
        int plane = t / 33;             // (di, cph)
        int jb4   = (t % 33) * 4;
        int di = plane >> 1, cph = plane & 1;
        int cp = cph * 8 + g;
        int j  = jb4 + cl;
        if (j < 130) {
            int gy = h + di - 1, gx = wb - 1 + j;
            float v0 = 0.0f, v1 = 0.0f;
            if (gy >= 0 && gy < HWDIM && gx >= 0 && gx < HWDIM) {
                v0 = xb[(2 * cp) * (HWDIM * HWDIM) + gy * HWDIM + gx];
                v1 = xb[(2 * cp + 1) * (HWDIM * HWDIM) + gy * HWDIM + gx];
            }
            __half2 hh = __halves2half2(__float2half(v0), __float2half(v1));
            int row = di * 130 + j;
            int w = ((cp >> 3) << 3) | ((cp & 3) << 1) | ((cp >> 2) & 1);
            int pos = w ^ (((row >> 1) & 1) << 3);
            *(uint32_t*)(smem + row * 64 + pos * 4) = *(uint32_t*)&hh;
        }
    }
    __syncthreads();

    // ---- precompute ALL masks (bit-exact fp32); halves split the 9 p's ----
    {
        const int px = tid & 127;
        const float fxv = fxp[n];
        const float bf  = __fmul_rn(blp[n], fxv);
        const float dC  = ds[132 + 1 + px];
        const bool validC = (dC != 0.0f);
        const float depthC = __fdiv_rn(bf, fminf(fmaxf(validC ? dC : 0.0f, 0.01f), 256.0f));
        const float grv    = __fdiv_rn(__fmul_rn(16.0f, depthC), fxv);
        const float halfv  = __fmul_rn(grv, 0.5f);
        const bool lo = ((px >> 3) & 1) == 0;
        const int widx = ((px >> 4) << 3) | (px & 7);
        const int p0 = (tid < 128) ? 0 : 5;
        const int p1 = (tid < 128) ? 5 : 9;
        for (int p = p0; p < p1; p++) {
            int di = p / 3, dj = p % 3;
            float dp = ds[di * 132 + dj + px];
            const bool valid = (dp != 0.0f) && validC;
            const float depth = __fdiv_rn(bf, fminf(fmaxf(valid ? dp : 0.0f, 0.01f), 256.0f));
            float m[3];
            m[0] = (fabsf(__fsub_rn(depth, __fadd_rn(depthC, grv))) <= halfv) ? 1.0f : 0.0f;
            const float ind = (fabsf(__fsub_rn(depth, depthC)) <= halfv) ? 1.0f : 0.0f;
            m[1] = valid ? ind : 1.0f;
            m[2] = (fabsf(__fsub_rn(depth, __fsub_rn(depthC, grv))) <= halfv) ? 1.0f : 0.0f;
#pragma unroll
            for (int i = 0; i < 3; i++) {
                float pm = __shfl_xor_sync(0xffffffffu, m[i], 8);
                if (lo) {
                    __half2 hh = __halves2half2(__float2half(m[i]), __float2half(pm));
                    pkw[p * 192 + i * 64 + widx] = *(uint32_t*)&hh;
                }
            }
        }
    }
    __syncthreads();

    // ---- barrier-free main loop ----
    float acc[2][4][4];
#pragma unroll
    for (int mt = 0; mt < 2; mt++)
#pragma unroll
        for (int n8 = 0; n8 < 4; n8++)
#pragma unroll
            for (int q = 0; q < 4; q++) acc[mt][n8][q] = 0.0f;

#pragma unroll 1
    for (int p = 0; p < KK; p++) {
        const int di = p / 3, dj = p % 3;

        uint32_t pw[3][2];
        bool sk[3];
#pragma unroll
        for (int i = 0; i < 3; i++) {
            pw[i][0] = pkw[p * 192 + i * 64 + (jb >> 5) * 16 + g];
            pw[i][1] = pkw[p * 192 + i * 64 + (jb >> 5) * 16 + 8 + g];
            sk[i] = !__any_sync(0xffffffffu, (pw[i][0] | pw[i][1]) != 0u);
        }
        if (sk[0] && sk[1] && sk[2]) continue;

        const int rowb = di * 130 + dj + jb;
#pragma unroll
        for (int ks = 0; ks < 2; ks++) {
            uint2 aL[2], aH[2];
#pragma unroll
            for (int mt = 0; mt < 2; mt++) {
                int r0 = rowb + mt * 16 + g;
                int pos0 = (ks * 8 + cl * 2) ^ (((r0 >> 1) & 1) << 3);
                aL[mt] = *(const uint2*)(smem + r0 * 64 + pos0 * 4);
                int r1 = r0 + 8;
                int pos1 = (ks * 8 + cl * 2) ^ (((r1 >> 1) & 1) << 3);
                aH[mt] = *(const uint2*)(smem + r1 * 64 + pos1 * 4);
            }
#pragma unroll
            for (int i = 0; i < 3; i++) {
                if (sk[i]) continue;
                const uint32_t* wf = g_wfrag + ((size_t)(p * 3 + i) * 64 + obase) * 16
                                   + ks * 8 + cl * 2;
                uint2 bv[4];
#pragma unroll
                for (int n8 = 0; n8 < 4; n8++)
                    bv[n8] = *(const uint2*)(wf + (n8 * 8 + g) * 16);
#pragma unroll
                for (int mt = 0; mt < 2; mt++) {
                    __half2 pp = *(__half2*)&pw[i][mt];
                    __half2 l2 = __half2half2(__low2half(pp));
                    __half2 h2 = __half2half2(__high2half(pp));
                    uint32_t ml = *(uint32_t*)&l2, mh = *(uint32_t*)&h2;
                    uint32_t am[4];
                    am[0] = hmul2u(aL[mt].x, ml);
                    am[1] = hmul2u(aH[mt].x, mh);
                    am[2] = hmul2u(aL[mt].y, ml);
                    am[3] = hmul2u(aH[mt].y, mh);
#pragma unroll
                    for (int n8 = 0; n8 < 4; n8++)
                        mma_f16(acc[mt][n8], am, (const uint32_t*)&bv[n8]);
                }
            }
        }
    }

    // ---- epilogue: acc -> smem transpose -> coalesced float4 stores ----
    __syncthreads();
    float* obuf = (float*)smem;   // [o][j], pitch 132 (overlays xs/ds/pk)
#pragma unroll
    for (int mt = 0; mt < 2; mt++) {
#pragma unroll
        for (int n8 = 0; n8 < 4; n8++) {
            int o = obase + n8 * 8 + cl * 2;
            int j = jb + mt * 16 + g;
            obuf[o * OB_PITCH + j]           = acc[mt][n8][0];
            obuf[(o + 1) * OB_PITCH + j]     = acc[mt][n8][1];
            obuf[o * OB_PITCH + j + 8]       = acc[mt][n8][2];
            obuf[(o + 1) * OB_PITCH + j + 8] = acc[mt][n8][3];
        }
    }
    __syncthreads();
#pragma unroll
    for (int it = 0; it < 8; it++) {
        int e  = tid + it * NTH;   // (o, j4): 64 x 32
        int o  = e >> 5;
        int j4 = e & 31;
        float4 v = *(const float4*)&obuf[o * OB_PITCH + j4 * 4];
        *(float4*)&out[((size_t)(n * OUT_C + o)) * (HWDIM * HWDIM)
                       + h * HWDIM + wb + j4 * 4] = v;
    }
}

extern "C" void kernel_launch(void* const* d_in, const int* in_sizes, int n_in,
                              void* d_out, int out_size) {
    const float* x    = (const float*)d_in[0];
    const float* disp = (const float*)d_in[1];
    const float* fx   = (const float*)d_in[2];
    const float* bl   = (const float*)d_in[3];
    const float* w0   = (const float*)d_in[4];
    const float* w1   = (const float*)d_in[5];
    const float* w2   = (const float*)d_in[6];
    float* out = (float*)d_out;

    prep_weights<<<(KK * 3 * OUT_C * 16 + 255) / 256, 256>>>(w0, w1, w2);
    conv25d_l1<<<1024, NTH>>>(x, disp, fx, bl, out);
}